// round 12
// baseline (speedup 1.0000x reference)
#include <cuda_runtime.h>
#include <cuda_bf16.h>
#include <math.h>
#include <stdint.h>

#define NN 8192
#define DD 128
#define KK 128

// ---------------- scratch (no allocations allowed) ----------------
__device__ __nv_bfloat16 g_G[(size_t)KK * DD * DD];   // 4 MB: G_k[i][j] = tril(tri,-1)*v[j], bf16
__device__ float g_v[KK * DD];                        // var = exp(tanh(logvar))
__device__ float g_cvec[KK * DD];                     // cvec_k[i] = sum_j G[i][j]*m[j]
__device__ float g_ld[KK];                            // logdet
__device__ float g_const[KK];                         // logdet + log_softmax(weigh)
__device__ float g_logits[(size_t)KK * NN];           // 4 MB, [k][n]

// ---------------- kernel A: per-component precompute ----------------
__global__ void __launch_bounds__(128) kprep(const float* __restrict__ means,
                                             const float* __restrict__ logvar,
                                             const float* __restrict__ tri) {
    int k = blockIdx.x;
    int tid = threadIdx.x;
    __shared__ float v_s[DD];
    __shared__ float m_s[DD];
    __shared__ float red[4];

    float lv = tanhf(logvar[k * DD + tid]);
    float v = expf(lv);
    v_s[tid] = v;
    g_v[k * DD + tid] = v;
    m_s[tid] = means[k * DD + tid];

    float ld = logf(fabsf(v) + 1e-8f);
#pragma unroll
    for (int o = 16; o > 0; o >>= 1) ld += __shfl_xor_sync(0xffffffffu, ld, o);
    if ((tid & 31) == 0) red[tid >> 5] = ld;
    __syncthreads();
    if (tid == 0) g_ld[k] = red[0] + red[1] + red[2] + red[3];

    // warp-per-row: build G row i (strict lower * v[j]) and cvec[i]
    int warp = tid >> 5, lane = tid & 31;
    const float* trik = tri + (size_t)k * DD * DD;
    __nv_bfloat16* Gk = g_G + (size_t)k * DD * DD;
    int j = lane * 4;
    for (int i = warp; i < DD; i += 4) {
        float4 t = *(const float4*)(trik + (size_t)i * DD + j);
        float g0 = (j + 0 < i) ? t.x * v_s[j + 0] : 0.f;
        float g1 = (j + 1 < i) ? t.y * v_s[j + 1] : 0.f;
        float g2 = (j + 2 < i) ? t.z * v_s[j + 2] : 0.f;
        float g3 = (j + 3 < i) ? t.w * v_s[j + 3] : 0.f;
        __nv_bfloat162 p0, p1;
        p0.x = __float2bfloat16_rn(g0); p0.y = __float2bfloat16_rn(g1);
        p1.x = __float2bfloat16_rn(g2); p1.y = __float2bfloat16_rn(g3);
        uint2 pk;
        pk.x = *(uint32_t*)&p0; pk.y = *(uint32_t*)&p1;
        *(uint2*)(Gk + (size_t)i * DD + j) = pk;
        float cp = g0 * m_s[j] + g1 * m_s[j + 1] + g2 * m_s[j + 2] + g3 * m_s[j + 3];
#pragma unroll
        for (int o = 16; o > 0; o >>= 1) cp += __shfl_xor_sync(0xffffffffu, cp, o);
        if (lane == 0) g_cvec[k * DD + i] = cp;
    }
}

// ---------------- kernel B: log_softmax(weigh) + const + output init ----------------
__global__ void __launch_bounds__(128) kconst(const float* __restrict__ weigh, float* out) {
    __shared__ float sm[KK];
    int t = threadIdx.x;
    float w = weigh[t];
    sm[t] = w;
    __syncthreads();
    for (int o = 64; o > 0; o >>= 1) { if (t < o) sm[t] = fmaxf(sm[t], sm[t + o]); __syncthreads(); }
    float mx = sm[0];
    __syncthreads();
    sm[t] = expf(w - mx);
    __syncthreads();
    for (int o = 64; o > 0; o >>= 1) { if (t < o) sm[t] += sm[t + o]; __syncthreads(); }
    float lse = mx + logf(sm[0]);
    g_const[t] = g_ld[t] + (w - lse);
    if (t == 0) out[0] = 64.0f * logf(6.283185307179586f);  // -logC = (D/2)*log(2*pi)
}

// ---------------- kernel C: main batched GEMM + fused q/logits epilogue ----------------
__device__ __forceinline__ void mma_bf16(float* c, const uint32_t* a, uint32_t b0, uint32_t b1) {
    asm volatile(
        "mma.sync.aligned.m16n8k16.row.col.f32.bf16.bf16.f32 "
        "{%0,%1,%2,%3}, {%4,%5,%6,%7}, {%8,%9}, {%0,%1,%2,%3};\n"
        : "+f"(c[0]), "+f"(c[1]), "+f"(c[2]), "+f"(c[3])
        : "r"(a[0]), "r"(a[1]), "r"(a[2]), "r"(a[3]), "r"(b0), "r"(b1));
}

#define LDB 136  // bf16 smem row stride (pad: stride 17 words -> conflict-free)
#define LDF 132  // fp32 smem row stride
#define SMEM_BYTES (2*128*LDB*2 + 128*LDF*4 + 3*128*4 + 2*128*4)  // 139776

__global__ void __launch_bounds__(256) kmain(const float* __restrict__ X,
                                             const float* __restrict__ means) {
    extern __shared__ char smem[];
    __nv_bfloat16* Xb = (__nv_bfloat16*)smem;                      // [128][136] bf16
    __nv_bfloat16* Gs = (__nv_bfloat16*)(smem + 128 * LDB * 2);    // [128][136] bf16
    float* Xs   = (float*)(smem + 2 * 128 * LDB * 2);              // [128][132] fp32
    float* cv_s = (float*)(smem + 2 * 128 * LDB * 2 + 128 * LDF * 4);
    float* m_s  = cv_s + 128;
    float* v_s  = m_s + 128;
    float* qsum = v_s + 128;                                        // [2][128]

    int tid = threadIdx.x;
    int n0 = blockIdx.x * 128;
    int k = blockIdx.y;

    // X tile -> fp32 smem (epilogue) + bf16 smem (MMA A operand)
#pragma unroll
    for (int it = 0; it < 16; ++it) {
        int idx = it * 256 + tid;
        int r = idx >> 5;
        int c = (idx & 31) * 4;
        float4 xv = *(const float4*)(X + (size_t)(n0 + r) * DD + c);
        *(float4*)(Xs + r * LDF + c) = xv;
        __nv_bfloat162 p0, p1;
        p0.x = __float2bfloat16_rn(xv.x); p0.y = __float2bfloat16_rn(xv.y);
        p1.x = __float2bfloat16_rn(xv.z); p1.y = __float2bfloat16_rn(xv.w);
        uint2 pk; pk.x = *(uint32_t*)&p0; pk.y = *(uint32_t*)&p1;
        *(uint2*)(Xb + r * LDB + c) = pk;
    }
    // G_k tile (B operand, row-major [i][j] == col-major KxN for mma .col)
    const __nv_bfloat16* Gk = g_G + (size_t)k * DD * DD;
#pragma unroll
    for (int it = 0; it < 8; ++it) {
        int idx = it * 256 + tid;
        int r = idx >> 4;
        int c = (idx & 15) * 8;
        uint4 gv = *(const uint4*)(Gk + (size_t)r * DD + c);
        *(uint4*)(Gs + r * LDB + c) = gv;
    }
    if (tid < 128) {
        cv_s[tid] = g_cvec[k * DD + tid];
        m_s[tid]  = means[k * DD + tid];
        v_s[tid]  = g_v[k * DD + tid];
    }
    __syncthreads();

    int warp = tid >> 5, lane = tid & 31;
    int wn = warp & 3;     // 4 warps along n (32 rows each)
    int wi = warp >> 2;    // 2 warps along i (64 cols each)
    int g = lane >> 2, tg = lane & 3;
    int rowA0 = wn * 32;
    int colB0 = wi * 64;

    float acc[2][8][4];
#pragma unroll
    for (int mi = 0; mi < 2; ++mi)
#pragma unroll
        for (int ni = 0; ni < 8; ++ni)
#pragma unroll
            for (int q = 0; q < 4; ++q) acc[mi][ni][q] = 0.f;

#pragma unroll
    for (int ks = 0; ks < 8; ++ks) {
        int j0 = ks * 16;
        uint32_t a[2][4];
#pragma unroll
        for (int mi = 0; mi < 2; ++mi) {
            const __nv_bfloat16* base = Xb + (size_t)(rowA0 + mi * 16) * LDB + j0;
            a[mi][0] = *(const uint32_t*)(base + (size_t)g * LDB + 2 * tg);
            a[mi][1] = *(const uint32_t*)(base + (size_t)(g + 8) * LDB + 2 * tg);
            a[mi][2] = *(const uint32_t*)(base + (size_t)g * LDB + 2 * tg + 8);
            a[mi][3] = *(const uint32_t*)(base + (size_t)(g + 8) * LDB + 2 * tg + 8);
        }
#pragma unroll
        for (int ni = 0; ni < 8; ++ni) {
            const __nv_bfloat16* bb = Gs + (size_t)(colB0 + ni * 8 + g) * LDB + j0 + 2 * tg;
            uint32_t b0 = *(const uint32_t*)bb;
            uint32_t b1 = *(const uint32_t*)(bb + 8);
            mma_bf16(acc[0][ni], a[0], b0, b1);
            mma_bf16(acc[1][ni], a[1], b0, b1);
        }
    }

    // Epilogue: z = (x-m)*v (fp32 exact) + (u = Xb@G^T - cvec); q = sum z^2 over i
    float rowsum[2][2] = {{0.f, 0.f}, {0.f, 0.f}};
#pragma unroll
    for (int mi = 0; mi < 2; ++mi) {
        int r0 = rowA0 + mi * 16 + g;
        int r1 = r0 + 8;
#pragma unroll
        for (int ni = 0; ni < 8; ++ni) {
            int c = colB0 + ni * 8 + 2 * tg;
            float cv0 = cv_s[c], cv1 = cv_s[c + 1];
            float mm0 = m_s[c],  mm1 = m_s[c + 1];
            float vv0 = v_s[c],  vv1 = v_s[c + 1];
            float z;
            z = (Xs[r0 * LDF + c]     - mm0) * vv0 + (acc[mi][ni][0] - cv0); rowsum[mi][0] += z * z;
            z = (Xs[r0 * LDF + c + 1] - mm1) * vv1 + (acc[mi][ni][1] - cv1); rowsum[mi][0] += z * z;
            z = (Xs[r1 * LDF + c]     - mm0) * vv0 + (acc[mi][ni][2] - cv0); rowsum[mi][1] += z * z;
            z = (Xs[r1 * LDF + c + 1] - mm1) * vv1 + (acc[mi][ni][3] - cv1); rowsum[mi][1] += z * z;
        }
    }
#pragma unroll
    for (int mi = 0; mi < 2; ++mi)
#pragma unroll
        for (int h = 0; h < 2; ++h) {
            float v = rowsum[mi][h];
            v += __shfl_xor_sync(0xffffffffu, v, 1);
            v += __shfl_xor_sync(0xffffffffu, v, 2);
            rowsum[mi][h] = v;
        }
    if (tg == 0) {
#pragma unroll
        for (int mi = 0; mi < 2; ++mi)
#pragma unroll
            for (int h = 0; h < 2; ++h)
                qsum[wi * 128 + rowA0 + mi * 16 + h * 8 + g] = rowsum[mi][h];
    }
    __syncthreads();
    if (tid < 128) {
        float q = qsum[tid] + qsum[128 + tid];
        g_logits[(size_t)k * NN + n0 + tid] = -0.5f * q + g_const[k];
    }
}

// ---------------- kernel D: logsumexp over K + mean ----------------
__global__ void __launch_bounds__(256) klse(float* __restrict__ out) {
    int n = blockIdx.x * 256 + threadIdx.x;
    const float* p = g_logits + n;
    float mx = -INFINITY, s = 0.f;
#pragma unroll 4
    for (int k = 0; k < KK; ++k) {
        float x = p[(size_t)k * NN];
        if (x > mx) { s = s * expf(mx - x) + 1.f; mx = x; }
        else        { s += expf(x - mx); }
    }
    float lse = mx + logf(s);
#pragma unroll
    for (int o = 16; o > 0; o >>= 1) lse += __shfl_xor_sync(0xffffffffu, lse, o);
    __shared__ float rs[8];
    int warp = threadIdx.x >> 5;
    if ((threadIdx.x & 31) == 0) rs[warp] = lse;
    __syncthreads();
    if (threadIdx.x == 0) {
        float s8 = 0.f;
#pragma unroll
        for (int i = 0; i < 8; ++i) s8 += rs[i];
        atomicAdd(out, -s8 * (1.0f / (float)NN));  // out = -logC - mean(lse)
    }
}

// ---------------- launch ----------------
extern "C" void kernel_launch(void* const* d_in, const int* in_sizes, int n_in,
                              void* d_out, int out_size) {
    (void)in_sizes; (void)n_in; (void)out_size;
    const float* X      = (const float*)d_in[0];
    const float* means  = (const float*)d_in[1];
    const float* logvar = (const float*)d_in[2];
    const float* tri    = (const float*)d_in[3];
    const float* weigh  = (const float*)d_in[4];
    float* out = (float*)d_out;

    cudaFuncSetAttribute(kmain, cudaFuncAttributeMaxDynamicSharedMemorySize, SMEM_BYTES);

    kprep<<<KK, 128>>>(means, logvar, tri);
    kconst<<<1, 128>>>(weigh, out);
    kmain<<<dim3(NN / 128, KK), 256, SMEM_BYTES>>>(X, means);
    klse<<<NN / 256, 256>>>(out);
}

// round 13
// speedup vs baseline: 1.4818x; 1.4818x over previous
#include <cuda_runtime.h>
#include <cuda_bf16.h>
#include <math.h>
#include <stdint.h>

#define NN 8192
#define DD 128
#define KK 128
#define LDB 136   // bf16 smem row stride (272B, 16B-multiple, conflict-free frag loads)
#define LDP 132   // fp32 padded stride (L in kprep, X in kproj)
#define LDC 129   // fp32 stride for C/M matrix in kprep
#define LDF 132

// ---------------- scratch (no allocations allowed) ----------------
__device__ __nv_bfloat16 g_S[(size_t)KK * DD * DD];   // 4 MB  S'_k (bf16, symmetric)
__device__ __nv_bfloat16 g_Xb[(size_t)NN * DD];       // 2 MB  X in bf16
__device__ __nv_bfloat16 g_WVb[KK * DD];              // wv_k = m + S'm (bf16) rows
__device__ float g_preT[(size_t)KK * NN];             // 4 MB  const_k - 0.5(||x||^2 + lin)
__device__ float g_logits[(size_t)KK * NN];           // 4 MB
__device__ float g_ldet[KK], g_e[KK], g_ck2[KK];
__device__ float g_pmx[8 * NN], g_ps[8 * NN];

// ---------------- kernel A: per-component precompute of S', wv, consts ----------------
__global__ void __launch_bounds__(256) kprep(const float* __restrict__ means,
                                             const float* __restrict__ logvar,
                                             const float* __restrict__ tri) {
    extern __shared__ float sh[];
    float* Ls = sh;                 // [128][LDP] strict-lower L
    float* Cs = sh + 128 * LDP;     // [128][LDC] C = L^T L, then M = L + L^T + C
    __shared__ float vs[128], ms[128], vmm[128], red[8];

    int k = blockIdx.x, tid = threadIdx.x;
    int lane = tid & 31, warp = tid >> 5;

    if (tid < 128) {
        float lv = tanhf(logvar[k * DD + tid]);
        float v = expf(lv);
        vs[tid] = v; ms[tid] = means[k * DD + tid]; vmm[tid] = v * ms[tid];
        float ld = logf(v + 1e-8f);
#pragma unroll
        for (int o = 16; o > 0; o >>= 1) ld += __shfl_xor_sync(0xffffffffu, ld, o);
        if (lane == 0) red[warp] = ld;
    }
    // load strict-lower L
    const float* trik = tri + (size_t)k * DD * DD;
#pragma unroll
    for (int it = 0; it < 16; ++it) {
        int idx = it * 256 + tid; int r = idx >> 5; int c = (idx & 31) * 4;
        float4 t = *(const float4*)(trik + (size_t)r * DD + c);
        Ls[r * LDP + c + 0] = (c + 0 < r) ? t.x : 0.f;
        Ls[r * LDP + c + 1] = (c + 1 < r) ? t.y : 0.f;
        Ls[r * LDP + c + 2] = (c + 2 < r) ? t.z : 0.f;
        Ls[r * LDP + c + 3] = (c + 3 < r) ? t.w : 0.f;
    }
    __syncthreads();
    if (tid == 0) g_ldet[k] = red[0] + red[1] + red[2] + red[3];

    // C = L^T L, upper 4x4 blocks (528 tasks), write both halves
    for (int task = tid; task < 528; task += 256) {
        int jb = (int)((sqrtf(8.f * task + 1.f) - 1.f) * 0.5f);
        while ((jb + 1) * (jb + 2) / 2 <= task) ++jb;
        while (jb * (jb + 1) / 2 > task) --jb;
        int ib = task - jb * (jb + 1) / 2;
        int i0 = ib * 4, j0 = jb * 4;
        float c[16];
#pragma unroll
        for (int q = 0; q < 16; ++q) c[q] = 0.f;
        for (int t = j0 + 1; t < 128; ++t) {
            float4 La = *(const float4*)&Ls[t * LDP + i0];
            float4 Lb = *(const float4*)&Ls[t * LDP + j0];
            c[ 0] += La.x * Lb.x; c[ 1] += La.x * Lb.y; c[ 2] += La.x * Lb.z; c[ 3] += La.x * Lb.w;
            c[ 4] += La.y * Lb.x; c[ 5] += La.y * Lb.y; c[ 6] += La.y * Lb.z; c[ 7] += La.y * Lb.w;
            c[ 8] += La.z * Lb.x; c[ 9] += La.z * Lb.y; c[10] += La.z * Lb.z; c[11] += La.z * Lb.w;
            c[12] += La.w * Lb.x; c[13] += La.w * Lb.y; c[14] += La.w * Lb.z; c[15] += La.w * Lb.w;
        }
#pragma unroll
        for (int a = 0; a < 4; ++a)
#pragma unroll
            for (int b = 0; b < 4; ++b) {
                Cs[(i0 + a) * LDC + j0 + b] = c[a * 4 + b];
                Cs[(j0 + b) * LDC + i0 + a] = c[a * 4 + b];
            }
    }
    __syncthreads();
    // M = C + L + L^T (in place)
#pragma unroll
    for (int it = 0; it < 64; ++it) {
        int idx = it * 256 + tid; int i = idx >> 7, j = idx & 127;
        Cs[i * LDC + j] += Ls[i * LDP + j] + Ls[j * LDP + i];
    }
    __syncthreads();
    // S'_ij = v_i v_j (delta + M)_ij - delta_ij  -> bf16
    __nv_bfloat16* Sk = g_S + (size_t)k * DD * DD;
#pragma unroll
    for (int it = 0; it < 32; ++it) {
        int idx = it * 256 + tid; int i = idx >> 6; int j = (idx & 63) * 2;
        float vi = vs[i];
        float M0 = Cs[i * LDC + j], M1 = Cs[i * LDC + j + 1];
        float s0 = vi * vs[j] * M0     + ((i == j)     ? (vi * vs[j] - 1.f)     : 0.f);
        float s1 = vi * vs[j + 1] * M1 + ((i == j + 1) ? (vi * vs[j + 1] - 1.f) : 0.f);
        __nv_bfloat162 p;
        p.x = __float2bfloat16_rn(s0); p.y = __float2bfloat16_rn(s1);
        *(__nv_bfloat162*)(Sk + (size_t)i * DD + j) = p;
    }
    // sm = S' m ; wv = m + sm ; e = m.(m+sm)
    if (tid < 128) {
        int i = tid;
        float acc = vs[i] * ms[i];
        for (int j = 0; j < 128; ++j) acc += vmm[j] * Cs[i * LDC + j];
        float smi = vs[i] * acc - ms[i];
        g_WVb[k * DD + i] = __float2bfloat16_rn(ms[i] + smi);
        float ep = ms[i] * (ms[i] + smi);
#pragma unroll
        for (int o = 16; o > 0; o >>= 1) ep += __shfl_xor_sync(0xffffffffu, ep, o);
        if (lane == 0) red[4 + warp] = ep;
    }
    __syncthreads();
    if (tid == 0) g_e[k] = red[4] + red[5] + red[6] + red[7];
}

// ---------------- kernel B: log_softmax + fold constants ----------------
__global__ void __launch_bounds__(128) kconst(const float* __restrict__ weigh, float* out) {
    __shared__ float sm[KK];
    int t = threadIdx.x;
    float w = weigh[t];
    sm[t] = w; __syncthreads();
    for (int o = 64; o > 0; o >>= 1) { if (t < o) sm[t] = fmaxf(sm[t], sm[t + o]); __syncthreads(); }
    float mx = sm[0]; __syncthreads();
    sm[t] = expf(w - mx); __syncthreads();
    for (int o = 64; o > 0; o >>= 1) { if (t < o) sm[t] += sm[t + o]; __syncthreads(); }
    float lse = mx + logf(sm[0]);
    g_ck2[t] = g_ldet[t] + (w - lse) - 0.5f * g_e[t];
    if (t == 0) out[0] = 64.0f * logf(6.283185307179586f);
}

// ---------------- shared mma helper ----------------
__device__ __forceinline__ void mma_bf16(float* c, const uint32_t* a, uint32_t b0, uint32_t b1) {
    asm volatile(
        "mma.sync.aligned.m16n8k16.row.col.f32.bf16.bf16.f32 "
        "{%0,%1,%2,%3}, {%4,%5,%6,%7}, {%8,%9}, {%0,%1,%2,%3};\n"
        : "+f"(c[0]), "+f"(c[1]), "+f"(c[2]), "+f"(c[3])
        : "r"(a[0]), "r"(a[1]), "r"(a[2]), "r"(a[3]), "r"(b0), "r"(b1));
}

__device__ __forceinline__ void cp16(void* smem_ptr, const void* gptr) {
    uint32_t s = (uint32_t)__cvta_generic_to_shared(smem_ptr);
    asm volatile("cp.async.cg.shared.global [%0], [%1], 16;\n" :: "r"(s), "l"(gptr));
}

// ---------------- kernel C: g_preT = const - 0.5(||x||^2 + lin); also X->bf16 ----------------
#define PROJ_SMEM (128*LDF*4 + 128*LDB*2 + 128*LDB*2)
__global__ void __launch_bounds__(256) kproj(const float* __restrict__ X) {
    extern __shared__ char smem[];
    float* Xs = (float*)smem;                                        // [128][LDF] fp32 (reused as preS)
    __nv_bfloat16* Xb = (__nv_bfloat16*)(smem + 128 * LDF * 4);      // [128][LDB]
    __nv_bfloat16* Wb = (__nv_bfloat16*)(smem + 128 * LDF * 4 + 128 * LDB * 2);
    __shared__ float rn2[128], ck2s[128];
    int tid = threadIdx.x; int n0 = blockIdx.x * 128;

#pragma unroll
    for (int it = 0; it < 16; ++it) {
        int idx = it * 256 + tid; int r = idx >> 5; int c = (idx & 31) * 4;
        float4 xv = *(const float4*)(X + (size_t)(n0 + r) * DD + c);
        *(float4*)(Xs + r * LDF + c) = xv;
        __nv_bfloat162 p0, p1;
        p0.x = __float2bfloat16_rn(xv.x); p0.y = __float2bfloat16_rn(xv.y);
        p1.x = __float2bfloat16_rn(xv.z); p1.y = __float2bfloat16_rn(xv.w);
        uint2 pk; pk.x = *(uint32_t*)&p0; pk.y = *(uint32_t*)&p1;
        *(uint2*)(Xb + r * LDB + c) = pk;
        *(uint2*)(g_Xb + (size_t)(n0 + r) * DD + c) = pk;
    }
#pragma unroll
    for (int it = 0; it < 8; ++it) {
        int idx = it * 256 + tid; int r = idx >> 4; int c = (idx & 15) * 8;
        uint4 gv = *(const uint4*)(g_WVb + r * DD + c);
        *(uint4*)(Wb + r * LDB + c) = gv;
    }
    if (tid < 128) ck2s[tid] = g_ck2[tid];
    __syncthreads();
    {   // exact fp32 row norms
        int r = tid >> 1, h = (tid & 1) * 64;
        float s = 0.f;
        for (int j = 0; j < 64; ++j) { float x = Xs[r * LDF + h + j]; s += x * x; }
        s += __shfl_xor_sync(0xffffffffu, s, 1);
        if (!(tid & 1)) rn2[r] = s;
    }
    __syncthreads();

    int warp = tid >> 5, lane = tid & 31;
    int wn = warp & 3, wi = warp >> 2;
    int g = lane >> 2, tg = lane & 3;
    int rowA0 = wn * 32, colB0 = wi * 64;

    float acc[2][8][4];
#pragma unroll
    for (int mi = 0; mi < 2; ++mi)
#pragma unroll
        for (int ni = 0; ni < 8; ++ni)
#pragma unroll
            for (int q = 0; q < 4; ++q) acc[mi][ni][q] = 0.f;

#pragma unroll
    for (int ks = 0; ks < 8; ++ks) {
        int j0 = ks * 16;
        uint32_t a[2][4];
#pragma unroll
        for (int mi = 0; mi < 2; ++mi) {
            const __nv_bfloat16* base = Xb + (size_t)(rowA0 + mi * 16) * LDB + j0;
            a[mi][0] = *(const uint32_t*)(base + (size_t)g * LDB + 2 * tg);
            a[mi][1] = *(const uint32_t*)(base + (size_t)(g + 8) * LDB + 2 * tg);
            a[mi][2] = *(const uint32_t*)(base + (size_t)g * LDB + 2 * tg + 8);
            a[mi][3] = *(const uint32_t*)(base + (size_t)(g + 8) * LDB + 2 * tg + 8);
        }
#pragma unroll
        for (int ni = 0; ni < 8; ++ni) {
            const __nv_bfloat16* bb = Wb + (size_t)(colB0 + ni * 8 + g) * LDB + j0 + 2 * tg;
            uint32_t b0 = *(const uint32_t*)bb;
            uint32_t b1 = *(const uint32_t*)(bb + 8);
            mma_bf16(acc[0][ni], a[0], b0, b1);
            mma_bf16(acc[1][ni], a[1], b0, b1);
        }
    }
    __syncthreads();           // done reading Xs for rn2 long ago; now reuse as preS
    float* preS = Xs;
#pragma unroll
    for (int mi = 0; mi < 2; ++mi) {
        int r0 = rowA0 + mi * 16 + g, r1 = r0 + 8;
#pragma unroll
        for (int ni = 0; ni < 8; ++ni) {
            int c = colB0 + ni * 8 + 2 * tg;
            preS[r0 * LDF + c]     = acc[mi][ni][0] + ck2s[c]     - 0.5f * rn2[r0];
            preS[r0 * LDF + c + 1] = acc[mi][ni][1] + ck2s[c + 1] - 0.5f * rn2[r0];
            preS[r1 * LDF + c]     = acc[mi][ni][2] + ck2s[c]     - 0.5f * rn2[r1];
            preS[r1 * LDF + c + 1] = acc[mi][ni][3] + ck2s[c + 1] - 0.5f * rn2[r1];
        }
    }
    __syncthreads();
#pragma unroll
    for (int it = 0; it < 64; ++it) {
        int c = it * 2 + (tid >> 7);
        int r = tid & 127;
        g_preT[(size_t)c * NN + n0 + r] = preS[r * LDF + c];
    }
}

// ---------------- kernel D: main GEMM (k-grouped, cp.async double-buffered) ----------------
#define MAIN_SMEM (3*128*LDB*2 + 1024)   // Xb + 2 S buffers + qsum = 105472
__global__ void __launch_bounds__(256, 2) kmain() {
    extern __shared__ char smem[];
    __nv_bfloat16* Xb = (__nv_bfloat16*)smem;
    __nv_bfloat16* Sbuf0 = (__nv_bfloat16*)(smem + 128 * LDB * 2);
    __nv_bfloat16* Sbuf1 = (__nv_bfloat16*)(smem + 2 * 128 * LDB * 2);
    float* qsum = (float*)(smem + 3 * 128 * LDB * 2);   // [2][128]

    int tid = threadIdx.x;
    int n0 = blockIdx.x * 128;
    int kbase = blockIdx.y * 8;

    {   // group 0: Xb + S[kbase]
        const __nv_bfloat16* xs = g_Xb + (size_t)n0 * DD;
        for (int i = tid; i < 2048; i += 256) {
            int r = i >> 4, ch = i & 15;
            cp16((char*)Xb + r * (LDB * 2) + ch * 16, xs + (size_t)r * DD + ch * 8);
        }
        const __nv_bfloat16* s0 = g_S + (size_t)kbase * DD * DD;
        for (int i = tid; i < 2048; i += 256) {
            int r = i >> 4, ch = i & 15;
            cp16((char*)Sbuf0 + r * (LDB * 2) + ch * 16, s0 + (size_t)r * DD + ch * 8);
        }
        asm volatile("cp.async.commit_group;\n");
    }

    int warp = tid >> 5, lane = tid & 31;
    int wn = warp & 3, wi = warp >> 2;
    int g = lane >> 2, tg = lane & 3;
    int rowA0 = wn * 32, colB0 = wi * 64;

    for (int kk = 0; kk < 8; ++kk) {
        __syncthreads();   // everyone done with previous compute (buffer reuse safe)
        if (kk < 7) {
            const __nv_bfloat16* sn = g_S + (size_t)(kbase + kk + 1) * DD * DD;
            __nv_bfloat16* dst = ((kk + 1) & 1) ? Sbuf1 : Sbuf0;
            for (int i = tid; i < 2048; i += 256) {
                int r = i >> 4, ch = i & 15;
                cp16((char*)dst + r * (LDB * 2) + ch * 16, sn + (size_t)r * DD + ch * 8);
            }
            asm volatile("cp.async.commit_group;\n");
            asm volatile("cp.async.wait_group 1;\n");
        } else {
            asm volatile("cp.async.wait_group 0;\n");
        }
        __syncthreads();
        const __nv_bfloat16* Gs = (kk & 1) ? Sbuf1 : Sbuf0;

        float acc[2][8][4];
#pragma unroll
        for (int mi = 0; mi < 2; ++mi)
#pragma unroll
            for (int ni = 0; ni < 8; ++ni)
#pragma unroll
                for (int q = 0; q < 4; ++q) acc[mi][ni][q] = 0.f;

#pragma unroll
        for (int ks = 0; ks < 8; ++ks) {
            int j0 = ks * 16;
            uint32_t a[2][4];
#pragma unroll
            for (int mi = 0; mi < 2; ++mi) {
                const __nv_bfloat16* base = Xb + (size_t)(rowA0 + mi * 16) * LDB + j0;
                a[mi][0] = *(const uint32_t*)(base + (size_t)g * LDB + 2 * tg);
                a[mi][1] = *(const uint32_t*)(base + (size_t)(g + 8) * LDB + 2 * tg);
                a[mi][2] = *(const uint32_t*)(base + (size_t)g * LDB + 2 * tg + 8);
                a[mi][3] = *(const uint32_t*)(base + (size_t)(g + 8) * LDB + 2 * tg + 8);
            }
#pragma unroll
            for (int ni = 0; ni < 8; ++ni) {
                const __nv_bfloat16* bb = Gs + (size_t)(colB0 + ni * 8 + g) * LDB + j0 + 2 * tg;
                uint32_t b0 = *(const uint32_t*)bb;
                uint32_t b1 = *(const uint32_t*)(bb + 8);
                mma_bf16(acc[0][ni], a[0], b0, b1);
                mma_bf16(acc[1][ni], a[1], b0, b1);
            }
        }

        // epilogue: dot_r = sum_c x[r][c] * u[r][c]   (x in bf16, exact enough)
        float rowsum[2][2] = {{0.f, 0.f}, {0.f, 0.f}};
#pragma unroll
        for (int mi = 0; mi < 2; ++mi) {
            int r0 = rowA0 + mi * 16 + g, r1 = r0 + 8;
#pragma unroll
            for (int ni = 0; ni < 8; ++ni) {
                int c = colB0 + ni * 8 + 2 * tg;
                __nv_bfloat162 x0 = *(const __nv_bfloat162*)(Xb + (size_t)r0 * LDB + c);
                __nv_bfloat162 x1 = *(const __nv_bfloat162*)(Xb + (size_t)r1 * LDB + c);
                rowsum[mi][0] += __bfloat162float(x0.x) * acc[mi][ni][0]
                               + __bfloat162float(x0.y) * acc[mi][ni][1];
                rowsum[mi][1] += __bfloat162float(x1.x) * acc[mi][ni][2]
                               + __bfloat162float(x1.y) * acc[mi][ni][3];
            }
        }
#pragma unroll
        for (int mi = 0; mi < 2; ++mi)
#pragma unroll
            for (int h = 0; h < 2; ++h) {
                float v = rowsum[mi][h];
                v += __shfl_xor_sync(0xffffffffu, v, 1);
                v += __shfl_xor_sync(0xffffffffu, v, 2);
                rowsum[mi][h] = v;
            }
        if (tg == 0) {
#pragma unroll
            for (int mi = 0; mi < 2; ++mi)
#pragma unroll
                for (int h = 0; h < 2; ++h)
                    qsum[wi * 128 + rowA0 + mi * 16 + h * 8 + g] = rowsum[mi][h];
        }
        __syncthreads();
        if (tid < 128) {
            float dot = qsum[tid] + qsum[128 + tid];
            size_t off = (size_t)(kbase + kk) * NN + n0 + tid;
            g_logits[off] = g_preT[off] - 0.5f * dot;
        }
    }
}

// ---------------- kernel E: split-K logsumexp ----------------
__global__ void __launch_bounds__(256) klse1() {
    int b = blockIdx.x, tid = threadIdx.x;
    int kc = b >> 5;
    int n = (b & 31) * 256 + tid;
    const float* p = g_logits + (size_t)(kc * 16) * NN + n;
    float mx = -INFINITY, s = 0.f;
#pragma unroll
    for (int j = 0; j < 16; ++j) {
        float x = p[(size_t)j * NN];
        if (x > mx) { s = s * expf(mx - x) + 1.f; mx = x; }
        else        { s += expf(x - mx); }
    }
    g_pmx[kc * NN + n] = mx;
    g_ps[kc * NN + n] = s;
}

__global__ void __launch_bounds__(256) klse2(float* __restrict__ out) {
    int n = blockIdx.x * 256 + threadIdx.x;
    float pm[8], pv[8], M = -INFINITY;
#pragma unroll
    for (int j = 0; j < 8; ++j) {
        pm[j] = g_pmx[j * NN + n]; pv[j] = g_ps[j * NN + n];
        M = fmaxf(M, pm[j]);
    }
    float s = 0.f;
#pragma unroll
    for (int j = 0; j < 8; ++j) s += pv[j] * expf(pm[j] - M);
    float lse = M + logf(s);
#pragma unroll
    for (int o = 16; o > 0; o >>= 1) lse += __shfl_xor_sync(0xffffffffu, lse, o);
    __shared__ float rs[8];
    if ((threadIdx.x & 31) == 0) rs[threadIdx.x >> 5] = lse;
    __syncthreads();
    if (threadIdx.x == 0) {
        float t = 0.f;
#pragma unroll
        for (int i = 0; i < 8; ++i) t += rs[i];
        atomicAdd(out, -t * (1.0f / (float)NN));
    }
}

// ---------------- launch ----------------
extern "C" void kernel_launch(void* const* d_in, const int* in_sizes, int n_in,
                              void* d_out, int out_size) {
    (void)in_sizes; (void)n_in; (void)out_size;
    const float* X      = (const float*)d_in[0];
    const float* means  = (const float*)d_in[1];
    const float* logvar = (const float*)d_in[2];
    const float* tri    = (const float*)d_in[3];
    const float* weigh  = (const float*)d_in[4];
    float* out = (float*)d_out;

    const int prep_smem = (128 * LDP + 128 * LDC) * 4;  // 133632
    cudaFuncSetAttribute(kprep, cudaFuncAttributeMaxDynamicSharedMemorySize, prep_smem);
    cudaFuncSetAttribute(kproj, cudaFuncAttributeMaxDynamicSharedMemorySize, PROJ_SMEM);
    cudaFuncSetAttribute(kmain, cudaFuncAttributeMaxDynamicSharedMemorySize, MAIN_SMEM);

    kprep<<<KK, 256, prep_smem>>>(means, logvar, tri);
    kconst<<<1, 128>>>(weigh, out);
    kproj<<<NN / 128, 256, PROJ_SMEM>>>(X);
    kmain<<<dim3(NN / 128, KK / 8), 256, MAIN_SMEM>>>();
    klse1<<<256, 256>>>();
    klse2<<<NN / 256, 256>>>(out);
}